// round 9
// baseline (speedup 1.0000x reference)
#include <cuda_runtime.h>
#include <math.h>

// Problem dims
#define NSAMP 3
#define SSYM  512
#define FDIM  20
#define NLIN  11
#define NOUT  9
#define HID   2048
#define HIN   13824      // NSAMP*SSYM*NOUT
#define NO_   (NSAMP*SSYM)

#define PF_BLOCKS    256   // prefetch blocks appended to cell0 grid
#define FRONT_PF_BLK 128   // prefetch blocks appended to front grid

// Scratch (device globals; no allocation allowed)
__device__ float g_v[HIN];
__device__ float g_h1[HID];
__device__ float g_h2[HID];
__device__ float g_h3[HID];
__device__ float g_lin[NO_];

__device__ __forceinline__ float sigmoidf_(float x) { return 1.0f / (1.0f + expf(-x)); }

// Streaming weight load: cache-streaming (last-use) so the big one-shot
// weight streams don't evict the prefetched next-stage weights from L2.
__device__ __forceinline__ float4 ld4_stream(const float4* p) {
    return __ldcs(p);
}

__device__ __forceinline__ void pf_l2(const char* p) {
    asm volatile("prefetch.global.L2 [%0];" :: "l"(p));
}

__device__ __forceinline__ void pf_region(const char* base, size_t bytes,
                                          size_t t0, size_t nth) {
    for (size_t off = t0 * 128; off < bytes; off += nth * 128)
        pf_l2(base + off);
}

// ---------------------------------------------------------------------------
// Kernel 1: front end. Blocks [0,512): one per symbol s, 128 threads.
// Blocks [512, 512+FRONT_PF_BLK): prefetch first 2KB of each used w_ih0 row
// (covers every worker thread's first loop chunk -> hides cell0 cold start).
// ---------------------------------------------------------------------------
__global__ void front_kernel(const float* __restrict__ wax,
                             const float* __restrict__ blw,
                             const float* __restrict__ blb,
                             const float* __restrict__ w_ih0) {
    if (blockIdx.x >= SSYM) {
        const int t0  = (blockIdx.x - SSYM) * blockDim.x + threadIdx.x;
        const int nth = FRONT_PF_BLK * 128;
        const int LINES = 16;  // 2KB per row
        for (int l = t0; l < 6144 * LINES; l += nth) {
            int rr = l / LINES, ln = l % LINES;
            int r  = (rr < HID) ? rr : rr + HID;  // skip f rows [2048,4096)
            pf_l2((const char*)(w_ih0 + (size_t)r * HIN) + ln * 128);
        }
        return;
    }

    __shared__ float ctab[FDIM], stab[FDIM];
    __shared__ float sx [NSAMP][FDIM];
    __shared__ float sre[NSAMP][NLIN], sim[NSAMP][NLIN];
    __shared__ float szz[NSAMP][NOUT];

    const int s   = blockIdx.x;
    const int tid = threadIdx.x;

    if (tid < FDIM) {
        float th = 6.2831853071795864769f * (float)tid / 20.0f;
        ctab[tid] = cosf(th);
        stab[tid] = sinf(th);
    }
    __syncthreads();

    const int warp = tid >> 5, lane = tid & 31;
    if (warp < NSAMP) {
        const int b = warp;
        // InstanceNorm over F=20
        float x = 0.0f;
        if (lane < FDIM) x = wax[(b * SSYM + s) * FDIM + lane];
        float sum = x;
        #pragma unroll
        for (int off = 16; off; off >>= 1) sum += __shfl_xor_sync(0xffffffffu, sum, off);
        float mean = sum * (1.0f / 20.0f);
        float d = (lane < FDIM) ? (x - mean) : 0.0f;
        float sq = d * d;
        #pragma unroll
        for (int off = 16; off; off >>= 1) sq += __shfl_xor_sync(0xffffffffu, sq, off);
        float inv = rsqrtf(sq * (1.0f / 20.0f) + 1e-9f);
        if (lane < FDIM) sx[b][lane] = d * inv;
        __syncwarp();

        // rfft (direct DFT)
        if (lane < NLIN) {
            float re = 0.0f, im = 0.0f;
            #pragma unroll
            for (int n = 0; n < FDIM; n++) {
                int r = (lane * n) % FDIM;
                float xn = sx[b][n];
                re += xn * ctab[r];
                im -= xn * stab[r];
            }
            sre[b][lane] = re;
            sim[b][lane] = im;
        }
        __syncwarp();

        // Bilinear + leaky relu
        if (lane < NOUT) {
            const float* Bk = blw + lane * (NLIN * NLIN);
            float z = 0.0f;
            #pragma unroll
            for (int i = 0; i < NLIN; i++) {
                float t = 0.0f;
                #pragma unroll
                for (int j = 0; j < NLIN; j++) t = fmaf(Bk[i * NLIN + j], sim[b][j], t);
                z = fmaf(sre[b][i], t, z);
            }
            z += blb[lane];
            z = z > 0.0f ? z : 0.01f * z;
            szz[b][lane] = z;
        }
    }
    __syncthreads();

    // Softmax across b per (s,k)
    if (tid < NSAMP * NOUT) {
        const int b = tid / NOUT, k = tid % NOUT;
        float z0 = szz[0][k], z1 = szz[1][k], z2 = szz[2][k];
        float m  = fmaxf(z0, fmaxf(z1, z2));
        float e0 = expf(z0 - m), e1 = expf(z1 - m), e2 = expf(z2 - m);
        float den = e0 + e1 + e2;
        float eb  = (b == 0) ? e0 : (b == 1) ? e1 : e2;
        g_v[s * (NSAMP * NOUT) + b * NOUT + k] = eb / den;
    }
}

// ---------------------------------------------------------------------------
// Kernels 2-4: fused LSTM-cell matvec. One block per hidden unit j.
// f-gate rows never read (c0 = 0), w_hh never read (h0 = 0).
// h[j] = sigmoid(o)*tanh(sigmoid(i)*tanh(g)).
// STAGE 0 appends PF_BLOCKS prefetch blocks that pull the NEXT stages'
// weights into L2 while this (DRAM-unsaturated) kernel streams.
// ---------------------------------------------------------------------------
template<int IN, int NT, int STAGE>
__global__ void __launch_bounds__(NT)
lstm_cell_kernel(const float* __restrict__ W,
                 const float* __restrict__ b_ih,
                 const float* __restrict__ b_hh,
                 const float* __restrict__ pfA,   // next cell weights (or null)
                 const float* __restrict__ pfB,   // cell-after weights (or null)
                 const float* __restrict__ pfC) { // final linear weights (or null)
    if (STAGE == 0 && blockIdx.x >= HID) {
        const size_t nth = (size_t)PF_BLOCKS * NT;
        const size_t t0  = (size_t)(blockIdx.x - HID) * NT + threadIdx.x;
        const size_t GATE = (size_t)HID * HID * 4;   // bytes per gate block
        // Order by need: w_ih1 (i, then g+o), w_ih2, lin_w
        pf_region((const char*)pfA,                       GATE,     t0, nth);
        pf_region((const char*)pfA + 2 * GATE,            2 * GATE, t0, nth);
        pf_region((const char*)pfB,                       GATE,     t0, nth);
        pf_region((const char*)pfB + 2 * GATE,            2 * GATE, t0, nth);
        pf_region((const char*)pfC, (size_t)NO_ * HID * 4,          t0, nth);
        return;
    }

    const float* __restrict__ x =
        (STAGE == 0) ? g_v : (STAGE == 1) ? g_h1 : g_h2;
    float* __restrict__ hout =
        (STAGE == 0) ? g_h1 : (STAGE == 1) ? g_h2 : g_h3;

    const int j   = blockIdx.x;
    const int tid = threadIdx.x;

    const float4* __restrict__ x4 = (const float4*)x;
    const float4* __restrict__ w0 = (const float4*)(W + (size_t)j * IN);              // i
    const float4* __restrict__ w1 = (const float4*)(W + (size_t)(j + 2 * HID) * IN);  // g
    const float4* __restrict__ w2 = (const float4*)(W + (size_t)(j + 3 * HID) * IN);  // o

    constexpr int ITER = IN / 4 / NT;              // exact: 3456/128=27, 512/128=4
    constexpr int U    = (ITER % 4 == 0) ? 4 : 3;  // batch size
    constexpr int CH   = ITER / U;

    float acc0 = 0.0f, acc1 = 0.0f, acc2 = 0.0f;
    #pragma unroll 1
    for (int c = 0; c < CH; c++) {
        float4 xv[U], a[U], b[U], cc[U];
        #pragma unroll
        for (int u = 0; u < U; u++) {
            const int t = tid + (c * U + u) * NT;
            xv[u] = x4[t];
            a[u]  = ld4_stream(w0 + t);
            b[u]  = ld4_stream(w1 + t);
            cc[u] = ld4_stream(w2 + t);
        }
        #pragma unroll
        for (int u = 0; u < U; u++) {
            acc0 += a[u].x  * xv[u].x + a[u].y  * xv[u].y + a[u].z  * xv[u].z + a[u].w  * xv[u].w;
            acc1 += b[u].x  * xv[u].x + b[u].y  * xv[u].y + b[u].z  * xv[u].z + b[u].w  * xv[u].w;
            acc2 += cc[u].x * xv[u].x + cc[u].y * xv[u].y + cc[u].z * xv[u].z + cc[u].w * xv[u].w;
        }
    }

    #pragma unroll
    for (int off = 16; off; off >>= 1) {
        acc0 += __shfl_xor_sync(0xffffffffu, acc0, off);
        acc1 += __shfl_xor_sync(0xffffffffu, acc1, off);
        acc2 += __shfl_xor_sync(0xffffffffu, acc2, off);
    }
    __shared__ float red[NT / 32][3];
    const int warp = tid >> 5, lane = tid & 31;
    if (lane == 0) { red[warp][0] = acc0; red[warp][1] = acc1; red[warp][2] = acc2; }
    __syncthreads();
    if (tid == 0) {
        float di = 0.0f, dg = 0.0f, dob = 0.0f;
        #pragma unroll
        for (int w = 0; w < NT / 32; w++) { di += red[w][0]; dg += red[w][1]; dob += red[w][2]; }
        float gi = di  + b_ih[j]            + b_hh[j];
        float gg = dg  + b_ih[j + 2 * HID]  + b_hh[j + 2 * HID];
        float go = dob + b_ih[j + 3 * HID]  + b_hh[j + 3 * HID];
        float c  = sigmoidf_(gi) * tanhf(gg);
        hout[j]  = sigmoidf_(go) * tanhf(c);
    }
}

// ---------------------------------------------------------------------------
// Kernel 5: final linear. One block per output row (1536 blocks).
// ---------------------------------------------------------------------------
template<int NT>
__global__ void __launch_bounds__(NT)
linear_kernel(const float* __restrict__ W, const float* __restrict__ bias) {
    const int j   = blockIdx.x;
    const int tid = threadIdx.x;
    const float4* __restrict__ x4 = (const float4*)g_h3;
    const float4* __restrict__ wr = (const float4*)(W + (size_t)j * HID);

    constexpr int ITER = HID / 4 / NT;  // 4 @ NT=128
    float acc = 0.0f;
    float4 xv[ITER], a[ITER];
    #pragma unroll
    for (int u = 0; u < ITER; u++) {
        const int t = tid + u * NT;
        xv[u] = x4[t];
        a[u]  = ld4_stream(wr + t);
    }
    #pragma unroll
    for (int u = 0; u < ITER; u++)
        acc += a[u].x * xv[u].x + a[u].y * xv[u].y + a[u].z * xv[u].z + a[u].w * xv[u].w;

    #pragma unroll
    for (int off = 16; off; off >>= 1) acc += __shfl_xor_sync(0xffffffffu, acc, off);
    __shared__ float red[NT / 32];
    const int warp = tid >> 5, lane = tid & 31;
    if (lane == 0) red[warp] = acc;
    __syncthreads();
    if (tid == 0) {
        float s = 0.0f;
        #pragma unroll
        for (int w = 0; w < NT / 32; w++) s += red[w];
        g_lin[j] = s + bias[j];
    }
}

// ---------------------------------------------------------------------------
// Kernel 6: inorm over S=512 + leaky relu + softmax over S. 3 blocks x 512.
// ---------------------------------------------------------------------------
__device__ __forceinline__ float blk512_sum(float v, float* red) {
    __syncthreads();
    const int warp = threadIdx.x >> 5, lane = threadIdx.x & 31;
    #pragma unroll
    for (int off = 16; off; off >>= 1) v += __shfl_xor_sync(0xffffffffu, v, off);
    if (lane == 0) red[warp] = v;
    __syncthreads();
    float r = (threadIdx.x < 16) ? red[threadIdx.x] : 0.0f;
    if (warp == 0) {
        #pragma unroll
        for (int off = 8; off; off >>= 1) r += __shfl_xor_sync(0xffffffffu, r, off);
        if (lane == 0) red[0] = r;
    }
    __syncthreads();
    return red[0];
}

__device__ __forceinline__ float blk512_max(float v, float* red) {
    __syncthreads();
    const int warp = threadIdx.x >> 5, lane = threadIdx.x & 31;
    #pragma unroll
    for (int off = 16; off; off >>= 1) v = fmaxf(v, __shfl_xor_sync(0xffffffffu, v, off));
    if (lane == 0) red[warp] = v;
    __syncthreads();
    float r = (threadIdx.x < 16) ? red[threadIdx.x] : -3.4e38f;
    if (warp == 0) {
        #pragma unroll
        for (int off = 8; off; off >>= 1) r = fmaxf(r, __shfl_xor_sync(0xffffffffu, r, off));
        if (lane == 0) red[0] = r;
    }
    __syncthreads();
    return red[0];
}

__global__ void post_kernel(float* __restrict__ out) {
    __shared__ float red[16];
    const int b = blockIdx.x, tid = threadIdx.x;
    float x = g_lin[b * SSYM + tid];

    float mean = blk512_sum(x, red) * (1.0f / 512.0f);
    float d    = x - mean;
    float var  = blk512_sum(d * d, red) * (1.0f / 512.0f);
    float xn   = d * rsqrtf(var + 1e-9f);
    float lr   = xn > 0.0f ? xn : 0.01f * xn;
    float mx   = blk512_max(lr, red);
    float e    = expf(lr - mx);
    float den  = blk512_sum(e, red);
    out[b * SSYM + tid] = e / den;
}

// ---------------------------------------------------------------------------
// Launch
// ---------------------------------------------------------------------------
extern "C" void kernel_launch(void* const* d_in, const int* in_sizes, int n_in,
                              void* d_out, int out_size) {
    const float* wax   = (const float*)d_in[0];
    const float* blw   = (const float*)d_in[1];
    const float* blb   = (const float*)d_in[2];
    const float* w_ih0 = (const float*)d_in[3];
    // d_in[4] = w_hh0 (unused: h0 == 0)
    const float* b_ih0 = (const float*)d_in[5];
    const float* b_hh0 = (const float*)d_in[6];
    const float* w_ih1 = (const float*)d_in[7];
    const float* b_ih1 = (const float*)d_in[9];
    const float* b_hh1 = (const float*)d_in[10];
    const float* w_ih2 = (const float*)d_in[11];
    const float* b_ih2 = (const float*)d_in[13];
    const float* b_hh2 = (const float*)d_in[14];
    const float* lin_w = (const float*)d_in[15];
    const float* lin_b = (const float*)d_in[16];

    front_kernel<<<SSYM + FRONT_PF_BLK, 128>>>(wax, blw, blb, w_ih0);
    lstm_cell_kernel<HIN, 128, 0><<<HID + PF_BLOCKS, 128>>>(w_ih0, b_ih0, b_hh0,
                                                            w_ih1, w_ih2, lin_w);
    lstm_cell_kernel<HID, 128, 1><<<HID, 128>>>(w_ih1, b_ih1, b_hh1, 0, 0, 0);
    lstm_cell_kernel<HID, 128, 2><<<HID, 128>>>(w_ih2, b_ih2, b_hh2, 0, 0, 0);
    linear_kernel<128><<<NO_, 128>>>(lin_w, lin_b);
    post_kernel<<<NSAMP, 512>>>((float*)d_out);
}

// round 10
// speedup vs baseline: 1.0318x; 1.0318x over previous
#include <cuda_runtime.h>
#include <math.h>

// Problem dims
#define NSAMP 3
#define SSYM  512
#define FDIM  20
#define NLIN  11
#define NOUT  9
#define HID   2048
#define HIN   13824      // NSAMP*SSYM*NOUT
#define NO_   (NSAMP*SSYM)

// Scratch (device globals; no allocation allowed)
__device__ float g_v[HIN];
__device__ float g_h1[HID];
__device__ float g_h2[HID];
__device__ float g_h3[HID];
__device__ float g_lin[NO_];

__device__ __forceinline__ float sigmoidf_(float x) { return 1.0f / (1.0f + expf(-x)); }

__device__ __forceinline__ void pf_l2(const char* p) {
    asm volatile("prefetch.global.L2 [%0];" :: "l"(p));
}

__device__ __forceinline__ void pf_region(const char* base, size_t bytes,
                                          size_t t0, size_t nth) {
    for (size_t off = t0 * 128; off < bytes; off += nth * 128)
        pf_l2(base + off);
}

// ---------------------------------------------------------------------------
// Kernel 1: front end. One block per symbol s (512 blocks, 128 threads).
// (Exact R1 version — the 92.7us baseline's front.)
// ---------------------------------------------------------------------------
__global__ void front_kernel(const float* __restrict__ wax,
                             const float* __restrict__ blw,
                             const float* __restrict__ blb) {
    __shared__ float ctab[FDIM], stab[FDIM];
    __shared__ float sx [NSAMP][FDIM];
    __shared__ float sre[NSAMP][NLIN], sim[NSAMP][NLIN];
    __shared__ float szz[NSAMP][NOUT];

    const int s   = blockIdx.x;
    const int tid = threadIdx.x;

    if (tid < FDIM) {
        float th = 6.2831853071795864769f * (float)tid / 20.0f;
        ctab[tid] = cosf(th);
        stab[tid] = sinf(th);
    }
    __syncthreads();

    const int warp = tid >> 5, lane = tid & 31;
    if (warp < NSAMP) {
        const int b = warp;
        // InstanceNorm over F=20
        float x = 0.0f;
        if (lane < FDIM) x = wax[(b * SSYM + s) * FDIM + lane];
        float sum = x;
        #pragma unroll
        for (int off = 16; off; off >>= 1) sum += __shfl_xor_sync(0xffffffffu, sum, off);
        float mean = sum * (1.0f / 20.0f);
        float d = (lane < FDIM) ? (x - mean) : 0.0f;
        float sq = d * d;
        #pragma unroll
        for (int off = 16; off; off >>= 1) sq += __shfl_xor_sync(0xffffffffu, sq, off);
        float inv = rsqrtf(sq * (1.0f / 20.0f) + 1e-9f);
        if (lane < FDIM) sx[b][lane] = d * inv;
        __syncwarp();

        // rfft (direct DFT): X[m] = sum_n x[n] * exp(-2*pi*i*m*n/20)
        if (lane < NLIN) {
            float re = 0.0f, im = 0.0f;
            #pragma unroll
            for (int n = 0; n < FDIM; n++) {
                int r = (lane * n) % FDIM;
                float xn = sx[b][n];
                re += xn * ctab[r];
                im -= xn * stab[r];
            }
            sre[b][lane] = re;
            sim[b][lane] = im;
        }
        __syncwarp();

        // Bilinear + leaky relu
        if (lane < NOUT) {
            const float* Bk = blw + lane * (NLIN * NLIN);
            float z = 0.0f;
            #pragma unroll
            for (int i = 0; i < NLIN; i++) {
                float t = 0.0f;
                #pragma unroll
                for (int j = 0; j < NLIN; j++) t = fmaf(Bk[i * NLIN + j], sim[b][j], t);
                z = fmaf(sre[b][i], t, z);
            }
            z += blb[lane];
            z = z > 0.0f ? z : 0.01f * z;
            szz[b][lane] = z;
        }
    }
    __syncthreads();

    // Softmax across b (3 values) per (s,k)
    if (tid < NSAMP * NOUT) {
        const int b = tid / NOUT, k = tid % NOUT;
        float z0 = szz[0][k], z1 = szz[1][k], z2 = szz[2][k];
        float m  = fmaxf(z0, fmaxf(z1, z2));
        float e0 = expf(z0 - m), e1 = expf(z1 - m), e2 = expf(z2 - m);
        float den = e0 + e1 + e2;
        float eb  = (b == 0) ? e0 : (b == 1) ? e1 : e2;
        g_v[s * (NSAMP * NOUT) + b * NOUT + k] = eb / den;
    }
}

// ---------------------------------------------------------------------------
// Kernels 2-4: fused LSTM-cell matvec, R1 loop body (plain loads, simple
// strided loop — 32 regs, occ 74%). One block per hidden unit j.
// f-gate rows never read (c0 = 0), w_hh never read (h0 = 0).
// h[j] = sigmoid(o)*tanh(sigmoid(i)*tanh(g)).
//
// NEW vs R1: PFB rider blocks appended to cell1 (prefetch w_ih2 used gates,
// 50MB; cell1's own stream is only 50MB so both fit in 126MB L2 and DRAM is
// ~45% idle during cell1) and to cell2 (prefetch lin_w, 12.6MB).
// ---------------------------------------------------------------------------
template<int IN, int NT, int STAGE, int PFB>
__global__ void __launch_bounds__(NT)
lstm_cell_kernel(const float* __restrict__ W,
                 const float* __restrict__ b_ih,
                 const float* __restrict__ b_hh,
                 const float* __restrict__ pfA) {  // prefetch target (or null)
    if (PFB > 0 && blockIdx.x >= HID) {
        const size_t nth = (size_t)PFB * NT;
        const size_t t0  = (size_t)(blockIdx.x - HID) * NT + threadIdx.x;
        if (STAGE == 1) {
            // w_ih2: i gate [0,GATE), g+o gates [2*GATE,4*GATE)
            const size_t GATE = (size_t)HID * HID * 4;
            pf_region((const char*)pfA,            GATE,     t0, nth);
            pf_region((const char*)pfA + 2 * GATE, 2 * GATE, t0, nth);
        } else {
            // lin_w
            pf_region((const char*)pfA, (size_t)NO_ * HID * 4, t0, nth);
        }
        return;
    }

    const float* __restrict__ x =
        (STAGE == 0) ? g_v : (STAGE == 1) ? g_h1 : g_h2;
    float* __restrict__ hout =
        (STAGE == 0) ? g_h1 : (STAGE == 1) ? g_h2 : g_h3;

    const int j   = blockIdx.x;
    const int tid = threadIdx.x;

    const float4* __restrict__ x4 = (const float4*)x;
    const float4* __restrict__ w0 = (const float4*)(W + (size_t)j * IN);              // i
    const float4* __restrict__ w1 = (const float4*)(W + (size_t)(j + 2 * HID) * IN);  // g
    const float4* __restrict__ w2 = (const float4*)(W + (size_t)(j + 3 * HID) * IN);  // o

    float acc0 = 0.0f, acc1 = 0.0f, acc2 = 0.0f;
    for (int t = tid; t < IN / 4; t += NT) {
        float4 v4 = x4[t];
        float4 a = w0[t];
        acc0 += a.x * v4.x + a.y * v4.y + a.z * v4.z + a.w * v4.w;
        float4 b = w1[t];
        acc1 += b.x * v4.x + b.y * v4.y + b.z * v4.z + b.w * v4.w;
        float4 c = w2[t];
        acc2 += c.x * v4.x + c.y * v4.y + c.z * v4.z + c.w * v4.w;
    }

    #pragma unroll
    for (int off = 16; off; off >>= 1) {
        acc0 += __shfl_xor_sync(0xffffffffu, acc0, off);
        acc1 += __shfl_xor_sync(0xffffffffu, acc1, off);
        acc2 += __shfl_xor_sync(0xffffffffu, acc2, off);
    }
    __shared__ float red[NT / 32][3];
    const int warp = tid >> 5, lane = tid & 31;
    if (lane == 0) { red[warp][0] = acc0; red[warp][1] = acc1; red[warp][2] = acc2; }
    __syncthreads();
    if (tid == 0) {
        float di = 0.0f, dg = 0.0f, dob = 0.0f;
        #pragma unroll
        for (int w = 0; w < NT / 32; w++) { di += red[w][0]; dg += red[w][1]; dob += red[w][2]; }
        float gi = di  + b_ih[j]            + b_hh[j];
        float gg = dg  + b_ih[j + 2 * HID]  + b_hh[j + 2 * HID];
        float go = dob + b_ih[j + 3 * HID]  + b_hh[j + 3 * HID];
        float c  = sigmoidf_(gi) * tanhf(gg);
        hout[j]  = sigmoidf_(go) * tanhf(c);
    }
}

// ---------------------------------------------------------------------------
// Kernel 5: final linear. One block per output row (1536 blocks). R1 version.
// ---------------------------------------------------------------------------
template<int NT>
__global__ void __launch_bounds__(NT)
linear_kernel(const float* __restrict__ W, const float* __restrict__ bias) {
    const int j   = blockIdx.x;
    const int tid = threadIdx.x;
    const float4* __restrict__ x4 = (const float4*)g_h3;
    const float4* __restrict__ wr = (const float4*)(W + (size_t)j * HID);
    float acc = 0.0f;
    for (int t = tid; t < HID / 4; t += NT) {
        float4 v4 = x4[t];
        float4 a  = wr[t];
        acc += a.x * v4.x + a.y * v4.y + a.z * v4.z + a.w * v4.w;
    }
    #pragma unroll
    for (int off = 16; off; off >>= 1) acc += __shfl_xor_sync(0xffffffffu, acc, off);
    __shared__ float red[NT / 32];
    const int warp = tid >> 5, lane = tid & 31;
    if (lane == 0) red[warp] = acc;
    __syncthreads();
    if (tid == 0) {
        float s = 0.0f;
        #pragma unroll
        for (int w = 0; w < NT / 32; w++) s += red[w];
        g_lin[j] = s + bias[j];
    }
}

// ---------------------------------------------------------------------------
// Kernel 6: inorm over S=512 + leaky relu + softmax over S. 3 blocks x 512.
// ---------------------------------------------------------------------------
__device__ __forceinline__ float blk512_sum(float v, float* red) {
    __syncthreads();
    const int warp = threadIdx.x >> 5, lane = threadIdx.x & 31;
    #pragma unroll
    for (int off = 16; off; off >>= 1) v += __shfl_xor_sync(0xffffffffu, v, off);
    if (lane == 0) red[warp] = v;
    __syncthreads();
    float r = (threadIdx.x < 16) ? red[threadIdx.x] : 0.0f;
    if (warp == 0) {
        #pragma unroll
        for (int off = 8; off; off >>= 1) r += __shfl_xor_sync(0xffffffffu, r, off);
        if (lane == 0) red[0] = r;
    }
    __syncthreads();
    return red[0];
}

__device__ __forceinline__ float blk512_max(float v, float* red) {
    __syncthreads();
    const int warp = threadIdx.x >> 5, lane = threadIdx.x & 31;
    #pragma unroll
    for (int off = 16; off; off >>= 1) v = fmaxf(v, __shfl_xor_sync(0xffffffffu, v, off));
    if (lane == 0) red[warp] = v;
    __syncthreads();
    float r = (threadIdx.x < 16) ? red[threadIdx.x] : -3.4e38f;
    if (warp == 0) {
        #pragma unroll
        for (int off = 8; off; off >>= 1) r = fmaxf(r, __shfl_xor_sync(0xffffffffu, r, off));
        if (lane == 0) red[0] = r;
    }
    __syncthreads();
    return red[0];
}

__global__ void post_kernel(float* __restrict__ out) {
    __shared__ float red[16];
    const int b = blockIdx.x, tid = threadIdx.x;
    float x = g_lin[b * SSYM + tid];

    float mean = blk512_sum(x, red) * (1.0f / 512.0f);
    float d    = x - mean;
    float var  = blk512_sum(d * d, red) * (1.0f / 512.0f);
    float xn   = d * rsqrtf(var + 1e-9f);
    float lr   = xn > 0.0f ? xn : 0.01f * xn;
    float mx   = blk512_max(lr, red);
    float e    = expf(lr - mx);
    float den  = blk512_sum(e, red);
    out[b * SSYM + tid] = e / den;
}

// ---------------------------------------------------------------------------
// Launch
// ---------------------------------------------------------------------------
extern "C" void kernel_launch(void* const* d_in, const int* in_sizes, int n_in,
                              void* d_out, int out_size) {
    const float* wax   = (const float*)d_in[0];
    const float* blw   = (const float*)d_in[1];
    const float* blb   = (const float*)d_in[2];
    const float* w_ih0 = (const float*)d_in[3];
    // d_in[4] = w_hh0 (unused: h0 == 0)
    const float* b_ih0 = (const float*)d_in[5];
    const float* b_hh0 = (const float*)d_in[6];
    const float* w_ih1 = (const float*)d_in[7];
    const float* b_ih1 = (const float*)d_in[9];
    const float* b_hh1 = (const float*)d_in[10];
    const float* w_ih2 = (const float*)d_in[11];
    const float* b_ih2 = (const float*)d_in[13];
    const float* b_hh2 = (const float*)d_in[14];
    const float* lin_w = (const float*)d_in[15];
    const float* lin_b = (const float*)d_in[16];

    front_kernel<<<SSYM, 128>>>(wax, blw, blb);
    // cell0: exact R1 config (NT=256, no riders)
    lstm_cell_kernel<HIN, 256, 0, 0><<<HID, 256>>>(w_ih0, b_ih0, b_hh0, 0);
    // cell1: R1 worker config + 128 rider blocks prefetching w_ih2 (50MB)
    lstm_cell_kernel<HID, 128, 1, 128><<<HID + 128, 128>>>(w_ih1, b_ih1, b_hh1, w_ih2);
    // cell2: R1 worker config + 64 rider blocks prefetching lin_w (12.6MB)
    lstm_cell_kernel<HID, 128, 2, 64><<<HID + 64, 128>>>(w_ih2, b_ih2, b_hh2, lin_w);
    linear_kernel<128><<<NO_, 128>>>(lin_w, lin_b);
    post_kernel<<<NSAMP, 512>>>((float*)d_out);
}

// round 11
// speedup vs baseline: 1.0546x; 1.0221x over previous
#include <cuda_runtime.h>
#include <math.h>

// Problem dims
#define NSAMP 3
#define SSYM  512
#define FDIM  20
#define NLIN  11
#define NOUT  9
#define HID   2048
#define HIN   13824      // NSAMP*SSYM*NOUT
#define NO_   (NSAMP*SSYM)

// Scratch (device globals; no allocation allowed)
__device__ float g_v[HIN];
__device__ float g_h1[HID];
__device__ float g_h2[HID];
__device__ float g_h3[HID];
__device__ float g_lin[NO_];

__device__ __forceinline__ float sigmoidf_(float x) { return 1.0f / (1.0f + expf(-x)); }

// Weight load: L1-bypass (cache in L2 only). Weights have zero reuse; keeping
// them out of L1 removes L1tex fill/queue overhead from the streaming path.
__device__ __forceinline__ float4 ldw(const float4* p) { return __ldcg(p); }

// ---------------------------------------------------------------------------
// Kernel 1: front end. One block per symbol s (512 blocks, 128 threads).
// (Exact R1 version.)
// ---------------------------------------------------------------------------
__global__ void front_kernel(const float* __restrict__ wax,
                             const float* __restrict__ blw,
                             const float* __restrict__ blb) {
    __shared__ float ctab[FDIM], stab[FDIM];
    __shared__ float sx [NSAMP][FDIM];
    __shared__ float sre[NSAMP][NLIN], sim[NSAMP][NLIN];
    __shared__ float szz[NSAMP][NOUT];

    const int s   = blockIdx.x;
    const int tid = threadIdx.x;

    if (tid < FDIM) {
        float th = 6.2831853071795864769f * (float)tid / 20.0f;
        ctab[tid] = cosf(th);
        stab[tid] = sinf(th);
    }
    __syncthreads();

    const int warp = tid >> 5, lane = tid & 31;
    if (warp < NSAMP) {
        const int b = warp;
        // InstanceNorm over F=20
        float x = 0.0f;
        if (lane < FDIM) x = wax[(b * SSYM + s) * FDIM + lane];
        float sum = x;
        #pragma unroll
        for (int off = 16; off; off >>= 1) sum += __shfl_xor_sync(0xffffffffu, sum, off);
        float mean = sum * (1.0f / 20.0f);
        float d = (lane < FDIM) ? (x - mean) : 0.0f;
        float sq = d * d;
        #pragma unroll
        for (int off = 16; off; off >>= 1) sq += __shfl_xor_sync(0xffffffffu, sq, off);
        float inv = rsqrtf(sq * (1.0f / 20.0f) + 1e-9f);
        if (lane < FDIM) sx[b][lane] = d * inv;
        __syncwarp();

        // rfft (direct DFT): X[m] = sum_n x[n] * exp(-2*pi*i*m*n/20)
        if (lane < NLIN) {
            float re = 0.0f, im = 0.0f;
            #pragma unroll
            for (int n = 0; n < FDIM; n++) {
                int r = (lane * n) % FDIM;
                float xn = sx[b][n];
                re += xn * ctab[r];
                im -= xn * stab[r];
            }
            sre[b][lane] = re;
            sim[b][lane] = im;
        }
        __syncwarp();

        // Bilinear + leaky relu
        if (lane < NOUT) {
            const float* Bk = blw + lane * (NLIN * NLIN);
            float z = 0.0f;
            #pragma unroll
            for (int i = 0; i < NLIN; i++) {
                float t = 0.0f;
                #pragma unroll
                for (int j = 0; j < NLIN; j++) t = fmaf(Bk[i * NLIN + j], sim[b][j], t);
                z = fmaf(sre[b][i], t, z);
            }
            z += blb[lane];
            z = z > 0.0f ? z : 0.01f * z;
            szz[b][lane] = z;
        }
    }
    __syncthreads();

    // Softmax across b (3 values) per (s,k)
    if (tid < NSAMP * NOUT) {
        const int b = tid / NOUT, k = tid % NOUT;
        float z0 = szz[0][k], z1 = szz[1][k], z2 = szz[2][k];
        float m  = fmaxf(z0, fmaxf(z1, z2));
        float e0 = expf(z0 - m), e1 = expf(z1 - m), e2 = expf(z2 - m);
        float den = e0 + e1 + e2;
        float eb  = (b == 0) ? e0 : (b == 1) ? e1 : e2;
        g_v[s * (NSAMP * NOUT) + b * NOUT + k] = eb / den;
    }
}

// ---------------------------------------------------------------------------
// Kernels 2-4: fused LSTM-cell matvec (R1 structure). One block per hidden
// unit j. f-gate rows never read (c0 = 0), w_hh never read (h0 = 0).
// h[j] = sigmoid(o)*tanh(sigmoid(i)*tanh(g)).
// ONLY change vs R1: weight loads use __ldcg (L1 bypass).
// ---------------------------------------------------------------------------
template<int IN, int NT, int STAGE>
__global__ void __launch_bounds__(NT)
lstm_cell_kernel(const float* __restrict__ W,
                 const float* __restrict__ b_ih,
                 const float* __restrict__ b_hh) {
    const float* __restrict__ x =
        (STAGE == 0) ? g_v : (STAGE == 1) ? g_h1 : g_h2;
    float* __restrict__ hout =
        (STAGE == 0) ? g_h1 : (STAGE == 1) ? g_h2 : g_h3;

    const int j   = blockIdx.x;
    const int tid = threadIdx.x;

    const float4* __restrict__ x4 = (const float4*)x;
    const float4* __restrict__ w0 = (const float4*)(W + (size_t)j * IN);              // i
    const float4* __restrict__ w1 = (const float4*)(W + (size_t)(j + 2 * HID) * IN);  // g
    const float4* __restrict__ w2 = (const float4*)(W + (size_t)(j + 3 * HID) * IN);  // o

    float acc0 = 0.0f, acc1 = 0.0f, acc2 = 0.0f;
    for (int t = tid; t < IN / 4; t += NT) {
        float4 v4 = x4[t];
        float4 a = ldw(w0 + t);
        acc0 += a.x * v4.x + a.y * v4.y + a.z * v4.z + a.w * v4.w;
        float4 b = ldw(w1 + t);
        acc1 += b.x * v4.x + b.y * v4.y + b.z * v4.z + b.w * v4.w;
        float4 c = ldw(w2 + t);
        acc2 += c.x * v4.x + c.y * v4.y + c.z * v4.z + c.w * v4.w;
    }

    #pragma unroll
    for (int off = 16; off; off >>= 1) {
        acc0 += __shfl_xor_sync(0xffffffffu, acc0, off);
        acc1 += __shfl_xor_sync(0xffffffffu, acc1, off);
        acc2 += __shfl_xor_sync(0xffffffffu, acc2, off);
    }
    __shared__ float red[NT / 32][3];
    const int warp = tid >> 5, lane = tid & 31;
    if (lane == 0) { red[warp][0] = acc0; red[warp][1] = acc1; red[warp][2] = acc2; }
    __syncthreads();
    if (tid == 0) {
        float di = 0.0f, dg = 0.0f, dob = 0.0f;
        #pragma unroll
        for (int w = 0; w < NT / 32; w++) { di += red[w][0]; dg += red[w][1]; dob += red[w][2]; }
        float gi = di  + b_ih[j]            + b_hh[j];
        float gg = dg  + b_ih[j + 2 * HID]  + b_hh[j + 2 * HID];
        float go = dob + b_ih[j + 3 * HID]  + b_hh[j + 3 * HID];
        float c  = sigmoidf_(gi) * tanhf(gg);
        hout[j]  = sigmoidf_(go) * tanhf(c);
    }
}

// ---------------------------------------------------------------------------
// Kernel 5: final linear. One block per output row (1536 blocks).
// Weight loads via __ldcg.
// ---------------------------------------------------------------------------
template<int NT>
__global__ void __launch_bounds__(NT)
linear_kernel(const float* __restrict__ W, const float* __restrict__ bias) {
    const int j   = blockIdx.x;
    const int tid = threadIdx.x;
    const float4* __restrict__ x4 = (const float4*)g_h3;
    const float4* __restrict__ wr = (const float4*)(W + (size_t)j * HID);
    float acc = 0.0f;
    for (int t = tid; t < HID / 4; t += NT) {
        float4 v4 = x4[t];
        float4 a  = ldw(wr + t);
        acc += a.x * v4.x + a.y * v4.y + a.z * v4.z + a.w * v4.w;
    }
    #pragma unroll
    for (int off = 16; off; off >>= 1) acc += __shfl_xor_sync(0xffffffffu, acc, off);
    __shared__ float red[NT / 32];
    const int warp = tid >> 5, lane = tid & 31;
    if (lane == 0) red[warp] = acc;
    __syncthreads();
    if (tid == 0) {
        float s = 0.0f;
        #pragma unroll
        for (int w = 0; w < NT / 32; w++) s += red[w];
        g_lin[j] = s + bias[j];
    }
}

// ---------------------------------------------------------------------------
// Kernel 6: inorm over S=512 + leaky relu + softmax over S. 3 blocks x 512.
// ---------------------------------------------------------------------------
__device__ __forceinline__ float blk512_sum(float v, float* red) {
    __syncthreads();
    const int warp = threadIdx.x >> 5, lane = threadIdx.x & 31;
    #pragma unroll
    for (int off = 16; off; off >>= 1) v += __shfl_xor_sync(0xffffffffu, v, off);
    if (lane == 0) red[warp] = v;
    __syncthreads();
    float r = (threadIdx.x < 16) ? red[threadIdx.x] : 0.0f;
    if (warp == 0) {
        #pragma unroll
        for (int off = 8; off; off >>= 1) r += __shfl_xor_sync(0xffffffffu, r, off);
        if (lane == 0) red[0] = r;
    }
    __syncthreads();
    return red[0];
}

__device__ __forceinline__ float blk512_max(float v, float* red) {
    __syncthreads();
    const int warp = threadIdx.x >> 5, lane = threadIdx.x & 31;
    #pragma unroll
    for (int off = 16; off; off >>= 1) v = fmaxf(v, __shfl_xor_sync(0xffffffffu, v, off));
    if (lane == 0) red[warp] = v;
    __syncthreads();
    float r = (threadIdx.x < 16) ? red[threadIdx.x] : -3.4e38f;
    if (warp == 0) {
        #pragma unroll
        for (int off = 8; off; off >>= 1) r = fmaxf(r, __shfl_xor_sync(0xffffffffu, r, off));
        if (lane == 0) red[0] = r;
    }
    __syncthreads();
    return red[0];
}

__global__ void post_kernel(float* __restrict__ out) {
    __shared__ float red[16];
    const int b = blockIdx.x, tid = threadIdx.x;
    float x = g_lin[b * SSYM + tid];

    float mean = blk512_sum(x, red) * (1.0f / 512.0f);
    float d    = x - mean;
    float var  = blk512_sum(d * d, red) * (1.0f / 512.0f);
    float xn   = d * rsqrtf(var + 1e-9f);
    float lr   = xn > 0.0f ? xn : 0.01f * xn;
    float mx   = blk512_max(lr, red);
    float e    = expf(lr - mx);
    float den  = blk512_sum(e, red);
    out[b * SSYM + tid] = e / den;
}

// ---------------------------------------------------------------------------
// Launch
// ---------------------------------------------------------------------------
extern "C" void kernel_launch(void* const* d_in, const int* in_sizes, int n_in,
                              void* d_out, int out_size) {
    const float* wax   = (const float*)d_in[0];
    const float* blw   = (const float*)d_in[1];
    const float* blb   = (const float*)d_in[2];
    const float* w_ih0 = (const float*)d_in[3];
    // d_in[4] = w_hh0 (unused: h0 == 0)
    const float* b_ih0 = (const float*)d_in[5];
    const float* b_hh0 = (const float*)d_in[6];
    const float* w_ih1 = (const float*)d_in[7];
    const float* b_ih1 = (const float*)d_in[9];
    const float* b_hh1 = (const float*)d_in[10];
    const float* w_ih2 = (const float*)d_in[11];
    const float* b_ih2 = (const float*)d_in[13];
    const float* b_hh2 = (const float*)d_in[14];
    const float* lin_w = (const float*)d_in[15];
    const float* lin_b = (const float*)d_in[16];

    front_kernel<<<SSYM, 128>>>(wax, blw, blb);
    lstm_cell_kernel<HIN, 256, 0><<<HID, 256>>>(w_ih0, b_ih0, b_hh0);
    lstm_cell_kernel<HID, 128, 1><<<HID, 128>>>(w_ih1, b_ih1, b_hh1);
    lstm_cell_kernel<HID, 128, 2><<<HID, 128>>>(w_ih2, b_ih2, b_hh2);
    linear_kernel<128><<<NO_, 128>>>(lin_w, lin_b);
    post_kernel<<<NSAMP, 512>>>((float*)d_out);
}